// round 9
// baseline (speedup 1.0000x reference)
#include <cuda_runtime.h>
#include <cstdint>
#include <cstddef>

// Fixed shapes: n=512, H=512, B=256
#define BB 256
#define HH 512
#define NN 512
#define GBLK 256      // persistent blocks; 2 per SM (forced via launch_bounds)
#define NTHR 256
#define TSA 34        // activation smem stride (transposed [k][row])
#define TSW 18        // weight smem stride (transposed [k][col]), 16 cols + pad
#define NEG_INF (-1.0e9f)
#define F32_TINY 1.17549435e-38f

// -------- device scratch (no allocations allowed) --------
__device__ float    g_h0[2][BB * HH];
__device__ float    g_h1[2][BB * HH];
__device__ float    g_logits[BB * NN];
__device__ int      g_sel[BB];
__device__ unsigned g_avail[BB * (NN / 32)];
__device__ float    g_lp[BB];
__device__ float    g_rowsum[3 * HH];
__device__ unsigned g_bar_cnt;   // zero-init; self-restoring
__device__ unsigned g_bar_gen;

// -------- Threefry-2x32 (20 rounds), bit-exact JAX replica --------
__device__ __forceinline__ unsigned rotl32(unsigned v, int r) {
    return (v << r) | (v >> (32 - r));
}

__device__ __forceinline__ void tf2x32(unsigned ks0, unsigned ks1,
                                       unsigned x0, unsigned x1,
                                       unsigned& o0, unsigned& o1)
{
    unsigned ks2 = ks0 ^ ks1 ^ 0x1BD11BDAu;
    x0 += ks0; x1 += ks1;
#define TF_R4(a,b,c,d) \
    x0 += x1; x1 = rotl32(x1,(a)); x1 ^= x0; \
    x0 += x1; x1 = rotl32(x1,(b)); x1 ^= x0; \
    x0 += x1; x1 = rotl32(x1,(c)); x1 ^= x0; \
    x0 += x1; x1 = rotl32(x1,(d)); x1 ^= x0;
    TF_R4(13,15,26,6)   x0 += ks1; x1 += ks2 + 1u;
    TF_R4(17,29,16,24)  x0 += ks2; x1 += ks0 + 2u;
    TF_R4(13,15,26,6)   x0 += ks0; x1 += ks1 + 3u;
    TF_R4(17,29,16,24)  x0 += ks1; x1 += ks2 + 4u;
    TF_R4(13,15,26,6)   x0 += ks2; x1 += ks0 + 5u;
#undef TF_R4
    o0 = x0; o1 = x1;
}

// XLA lowers logistic(x) as 0.5 + 0.5*tanh(0.5*x); mirror that op graph.
__device__ __forceinline__ float jax_sigmoid(float x) {
    return __fadd_rn(0.5f, __fmul_rn(0.5f, tanhf(__fmul_rn(0.5f, x))));
}

// L2-coherent float4 load (persistent kernel: L1 may hold stale lines)
__device__ __forceinline__ float4 ldcg4(const float* p) {
    return __ldcg(reinterpret_cast<const float4*>(p));
}

// -------- packed f32x2 FMA: two IEEE fp32 FMAs per instruction --------
union f2u { float2 f; unsigned long long u; };

__device__ __forceinline__ float2 ffma2(float2 a, float2 b, float2 c) {
    f2u A, B, C, D;
    A.f = a; B.f = b; C.f = c;
    asm("fma.rn.f32x2 %0, %1, %2, %3;" : "=l"(D.u) : "l"(A.u), "l"(B.u), "l"(C.u));
    return D.f;
}
__device__ __forceinline__ float2 bc2(float a) { return make_float2(a, a); }

// transposed smem stores
__device__ __forceinline__ void st_act(float* buf, int lc, int lr, float4 v) {
    buf[(lc + 0) * TSA + lr] = v.x;
    buf[(lc + 1) * TSA + lr] = v.y;
    buf[(lc + 2) * TSA + lr] = v.z;
    buf[(lc + 3) * TSA + lr] = v.w;
}
__device__ __forceinline__ void st_w(float* buf, int kc, int jr, float4 v) {
    buf[(kc + 0) * TSW + jr] = v.x;
    buf[(kc + 1) * TSW + jr] = v.y;
    buf[(kc + 2) * TSW + jr] = v.z;
    buf[(kc + 3) * TSW + jr] = v.w;
}
__device__ __forceinline__ float2 lds2(const float* p) {
    return *reinterpret_cast<const float2*>(p);
}

// -------- software grid barrier (all GBLK blocks resident) --------
__device__ __forceinline__ void gsync() {
    __syncthreads();
    if (threadIdx.x == 0) {
        __threadfence();
        unsigned gen = *(volatile unsigned*)&g_bar_gen;
        if (atomicAdd(&g_bar_cnt, 1u) == GBLK - 1u) {
            atomicExch(&g_bar_cnt, 0u);
            __threadfence();
            atomicAdd(&g_bar_gen, 1u);
        } else {
            while (*(volatile unsigned*)&g_bar_gen == gen) { }
        }
        __threadfence();
    }
    __syncthreads();
}

// smem layout (floats): AS0[1088] AS1[1088] WS0..WS5[576 each] = 5632 floats
#define AS0 (SM)
#define AS1 (SM + 1088)
#define WS(g) (SM + 2176 + (g) * 576)

__global__ void __launch_bounds__(NTHR, 2) perm_persistent(
    const float* __restrict__ Wih0, const float* __restrict__ Whh0,
    const float* __restrict__ bih0, const float* __restrict__ bhh0,
    const float* __restrict__ Wih1, const float* __restrict__ Whh1,
    const float* __restrict__ bih1, const float* __restrict__ bhh1,
    const float* __restrict__ Wout, const float* __restrict__ bout,
    float* __restrict__ out)
{
    __shared__ float SM[5632];   // 22.5 KB -> 2 blocks/SM fits easily

    const int blk = blockIdx.x;
    const int tid = threadIdx.x;

    // ---------------- init (per-launch state reset) ----------------
    {
        for (int i = blk * NTHR + tid; i < BB * HH; i += GBLK * NTHR) {
            g_h0[0][i] = 0.0f;
            g_h1[0][i] = 0.0f;
        }
        if (tid == 0) g_lp[blk] = 0.0f;
        if (tid < 16) g_avail[blk * 16 + tid] = 0xFFFFFFFFu;
        int lane = tid & 31;
        int row = blk * 8 + (tid >> 5);
        if (row < 3 * HH) {
            const float* rp = Wih0 + (size_t)row * HH;
            float s = 0.0f;
            for (int k = lane; k < HH; k += 32) s = __fadd_rn(s, rp[k]);
#pragma unroll
            for (int off = 16; off > 0; off >>= 1)
                s = __fadd_rn(s, __shfl_xor_sync(0xFFFFFFFFu, s, off));
            if (lane == 0) g_rowsum[row] = s;
        }
    }
    gsync();

    // tile jobs: 8 batch tiles (32 rows) x 32 col tiles (16 cols) == GBLK
    const int jx = blk & 31;
    const int jy = blk >> 5;
    const int bm0 = jy * 32;
    const int jn0 = jx * 16;
    const int tx = tid & 7;          // col pair: 2*tx, 2*tx+1
    const int ty = tid >> 3;         // batch row: bm0 + ty
    const int lr = tid >> 3, lc = (tid & 7) << 2;     // act loader
    const int jrow = (tid >> 3) & 15, kcw = (tid & 7) << 2;  // weight loader

    // hoisted weight source pointers (fixed per block/thread)
    // layer0: buffers 0..2 <- Whh0 gates
    const int   l0gb   = tid >> 7;                       // 0 or 1
    const float* l0src0 = Whh0 + (size_t)(l0gb * HH + jn0 + jrow) * HH;
    const float* l0src1 = Whh0 + (size_t)(2 * HH + jn0 + jrow) * HH;  // tid<128
    float* l0dst0 = WS(l0gb);
    // layer1: buffers 0..2 Wih1, 3..5 Whh1; 3 passes of 2 buffers
    const float* l1src[3];
    float*       l1dst[3];
#pragma unroll
    for (int p = 0; p < 3; p++) {
        int gb = 2 * p + (tid >> 7);
        const float* base = (gb < 3) ? (Wih1 + (size_t)gb * HH * HH)
                                     : (Whh1 + (size_t)(gb - 3) * HH * HH);
        l1src[p] = base + (size_t)(jn0 + jrow) * HH;
        l1dst[p] = WS(gb);
    }
    const float* losrc = Wout + (size_t)(jn0 + jrow) * HH;  // tid<128

    for (int t = 0; t < NN; t++) {
        const int p = t & 1;
        const float* h0_in  = g_h0[p];
        float*       h0_out = g_h0[p ^ 1];
        const float* h1_in  = g_h1[p];
        float*       h1_out = g_h1[p ^ 1];

        // ---------------- layer 0: h0n = GRU(onehot(sel), h0) ----------------
        {
            // input-gate gather (1 batch row per thread)
            float gi[3][2];
            if (t == 0) {
#pragma unroll
                for (int g = 0; g < 3; g++)
#pragma unroll
                    for (int ni = 0; ni < 2; ni++)
                        gi[g][ni] = __ldcg(&g_rowsum[g * HH + jn0 + 2 * tx + ni]);
            } else {
                int xs = __ldcg(&g_sel[bm0 + ty]);
#pragma unroll
                for (int g = 0; g < 3; g++)
#pragma unroll
                    for (int ni = 0; ni < 2; ni++)
                        gi[g][ni] = __ldg(&Wih0[(size_t)(g * HH + jn0 + 2 * tx + ni) * HH + xs]);
            }

            float2 acc[3];
#pragma unroll
            for (int g = 0; g < 3; g++) acc[g] = make_float2(0.f, 0.f);

            float4 pa  = ldcg4(h0_in + (size_t)(bm0 + lr) * HH + lc);
            float4 pw0 = *reinterpret_cast<const float4*>(l0src0 + kcw);
            float4 pw1 = (tid < 128)
                       ? *reinterpret_cast<const float4*>(l0src1 + kcw)
                       : make_float4(0.f, 0.f, 0.f, 0.f);
#pragma unroll 1
            for (int k0 = 0; k0 < HH; k0 += 32) {
                st_act(AS0, lc, lr, pa);
                st_w(l0dst0, kcw, jrow, pw0);
                if (tid < 128) st_w(WS(2), kcw, jrow, pw1);
                __syncthreads();
                if (k0 + 32 < HH) {
                    int kn = k0 + 32;
                    pa  = ldcg4(h0_in + (size_t)(bm0 + lr) * HH + kn + lc);
                    pw0 = *reinterpret_cast<const float4*>(l0src0 + kn + kcw);
                    if (tid < 128)
                        pw1 = *reinterpret_cast<const float4*>(l0src1 + kn + kcw);
                }
#pragma unroll
                for (int k = 0; k < 32; k++) {
                    float2 a = bc2(AS0[k * TSA + ty]);
#pragma unroll
                    for (int g = 0; g < 3; g++)
                        acc[g] = ffma2(a, lds2(WS(g) + k * TSW + 2 * tx), acc[g]);
                }
                __syncthreads();
            }
            int b = bm0 + ty;
#pragma unroll
            for (int ni = 0; ni < 2; ni++) {
                int j = jn0 + 2 * tx + ni;
                float ir  = __fadd_rn(gi[0][ni], bih0[j]);
                float iz  = __fadd_rn(gi[1][ni], bih0[j + HH]);
                float inn = __fadd_rn(gi[2][ni], bih0[j + 2 * HH]);
                float hr = __fadd_rn(ni ? acc[0].y : acc[0].x, bhh0[j]);
                float hz = __fadd_rn(ni ? acc[1].y : acc[1].x, bhh0[j + HH]);
                float hn = __fadd_rn(ni ? acc[2].y : acc[2].x, bhh0[j + 2 * HH]);
                float r  = jax_sigmoid(__fadd_rn(ir, hr));
                float z  = jax_sigmoid(__fadd_rn(iz, hz));
                float ng = tanhf(__fadd_rn(inn, __fmul_rn(r, hn)));
                float hp = __ldcg(&h0_in[(size_t)b * HH + j]);
                h0_out[(size_t)b * HH + j] =
                    __fadd_rn(__fmul_rn(__fsub_rn(1.0f, z), ng), __fmul_rn(z, hp));
            }
        }
        gsync();

        // ---------------- layer 1: h1n = GRU(h0n, h1) ----------------
        {
            float2 accI[3], accH[3];
#pragma unroll
            for (int g = 0; g < 3; g++) {
                accI[g] = make_float2(0.f, 0.f);
                accH[g] = make_float2(0.f, 0.f);
            }
            float4 pa0 = ldcg4(h0_out + (size_t)(bm0 + lr) * HH + lc);
            float4 pa1 = ldcg4(h1_in  + (size_t)(bm0 + lr) * HH + lc);
            float4 pw[3];
#pragma unroll
            for (int q = 0; q < 3; q++)
                pw[q] = *reinterpret_cast<const float4*>(l1src[q] + kcw);
#pragma unroll 1
            for (int k0 = 0; k0 < HH; k0 += 32) {
                st_act(AS0, lc, lr, pa0);
                st_act(AS1, lc, lr, pa1);
#pragma unroll
                for (int q = 0; q < 3; q++) st_w(l1dst[q], kcw, jrow, pw[q]);
                __syncthreads();
                if (k0 + 32 < HH) {
                    int kn = k0 + 32;
                    pa0 = ldcg4(h0_out + (size_t)(bm0 + lr) * HH + kn + lc);
                    pa1 = ldcg4(h1_in  + (size_t)(bm0 + lr) * HH + kn + lc);
#pragma unroll
                    for (int q = 0; q < 3; q++)
                        pw[q] = *reinterpret_cast<const float4*>(l1src[q] + kn + kcw);
                }
#pragma unroll
                for (int k = 0; k < 32; k++) {
                    float2 xv = bc2(AS0[k * TSA + ty]);
                    float2 hv = bc2(AS1[k * TSA + ty]);
#pragma unroll
                    for (int g = 0; g < 3; g++) {
                        accI[g] = ffma2(xv, lds2(WS(g)     + k * TSW + 2 * tx), accI[g]);
                        accH[g] = ffma2(hv, lds2(WS(3 + g) + k * TSW + 2 * tx), accH[g]);
                    }
                }
                __syncthreads();
            }
            int b = bm0 + ty;
#pragma unroll
            for (int ni = 0; ni < 2; ni++) {
                int j = jn0 + 2 * tx + ni;
                float ir  = __fadd_rn(ni ? accI[0].y : accI[0].x, bih1[j]);
                float iz  = __fadd_rn(ni ? accI[1].y : accI[1].x, bih1[j + HH]);
                float inn = __fadd_rn(ni ? accI[2].y : accI[2].x, bih1[j + 2 * HH]);
                float hr  = __fadd_rn(ni ? accH[0].y : accH[0].x, bhh1[j]);
                float hz  = __fadd_rn(ni ? accH[1].y : accH[1].x, bhh1[j + HH]);
                float hn  = __fadd_rn(ni ? accH[2].y : accH[2].x, bhh1[j + 2 * HH]);
                float r  = jax_sigmoid(__fadd_rn(ir, hr));
                float z  = jax_sigmoid(__fadd_rn(iz, hz));
                float ng = tanhf(__fadd_rn(inn, __fmul_rn(r, hn)));
                float hp = __ldcg(&h1_in[(size_t)b * HH + j]);
                h1_out[(size_t)b * HH + j] =
                    __fadd_rn(__fmul_rn(__fsub_rn(1.0f, z), ng), __fmul_rn(z, hp));
            }
        }
        gsync();

        // ---------------- logits = h1n @ W_out^T + b_out ----------------
        {
            float2 acc = make_float2(0.f, 0.f);
            float4 pa = ldcg4(h1_out + (size_t)(bm0 + lr) * HH + lc);
            float4 pb = (tid < 128)
                      ? *reinterpret_cast<const float4*>(losrc + kcw)
                      : make_float4(0.f, 0.f, 0.f, 0.f);
#pragma unroll 1
            for (int k0 = 0; k0 < HH; k0 += 32) {
                st_act(AS0, lc, lr, pa);
                if (tid < 128) st_w(WS(0), kcw, jrow, pb);
                __syncthreads();
                if (k0 + 32 < HH) {
                    int kn = k0 + 32;
                    pa = ldcg4(h1_out + (size_t)(bm0 + lr) * HH + kn + lc);
                    if (tid < 128)
                        pb = *reinterpret_cast<const float4*>(losrc + kn + kcw);
                }
#pragma unroll
                for (int k = 0; k < 32; k++) {
                    float2 a = bc2(AS0[k * TSA + ty]);
                    acc = ffma2(a, lds2(WS(0) + k * TSW + 2 * tx), acc);
                }
                __syncthreads();
            }
            int b = bm0 + ty;
#pragma unroll
            for (int ni = 0; ni < 2; ni++) {
                int c = jn0 + 2 * tx + ni;
                g_logits[(size_t)b * NN + c] =
                    __fadd_rn(ni ? acc.y : acc.x, bout[c]);
            }
        }
        gsync();

        // ------- sample: 1 batch row per block, shuffle reductions -------
        {
            float* W_S = SM;                 // [8] per-warp argmax value
            int*   W_I = (int*)(SM + 8);     // [8] per-warp argmax index
            float* W_V = SM + 16;            // [8] per-warp vmax
            float* W_E = SM + 24;            // [8] per-warp expsum

            const int b   = blk;
            const int wid = tid >> 5;

            unsigned sk0, sk1;
            tf2x32(0u, 42u, 0u, (unsigned)t, sk0, sk1);   // step key

            float lg0 = __ldcg(&g_logits[(size_t)b * NN + tid]);
            float lg1 = __ldcg(&g_logits[(size_t)b * NN + tid + 256]);
            unsigned w0 = g_avail[b * 16 + (tid >> 5)];
            unsigned w1 = g_avail[b * 16 + (tid >> 5) + 8];
            float v0 = ((w0 >> (tid & 31)) & 1u) ? lg0 : NEG_INF;
            float v1 = ((w1 >> (tid & 31)) & 1u) ? lg1 : NEG_INF;

            unsigned o0, o1, bits;
            tf2x32(sk0, sk1, 0u, (unsigned)(b * NN + tid), o0, o1);
            bits = o0 ^ o1;
            float f0 = __fsub_rn(__uint_as_float((bits >> 9) | 0x3F800000u), 1.0f);
            float g0 = -logf(-logf(fmaxf(f0, F32_TINY)));
            tf2x32(sk0, sk1, 0u, (unsigned)(b * NN + tid + 256), o0, o1);
            bits = o0 ^ o1;
            float f1 = __fsub_rn(__uint_as_float((bits >> 9) | 0x3F800000u), 1.0f);
            float g1 = -logf(-logf(fmaxf(f1, F32_TINY)));

            float s0 = __fadd_rn(g0, v0);
            float s1 = __fadd_rn(g1, v1);
            float bs; int bi;
            if (s1 > s0) { bs = s1; bi = tid + 256; } else { bs = s0; bi = tid; }
            float lv = fmaxf(v0, v1);
#pragma unroll
            for (int off = 16; off > 0; off >>= 1) {
                float os = __shfl_xor_sync(0xFFFFFFFFu, bs, off);
                int   oi = __shfl_xor_sync(0xFFFFFFFFu, bi, off);
                float ov = __shfl_xor_sync(0xFFFFFFFFu, lv, off);
                if (os > bs || (os == bs && oi < bi)) { bs = os; bi = oi; }
                lv = fmaxf(lv, ov);
            }
            if ((tid & 31) == 0) { W_S[wid] = bs; W_I[wid] = bi; W_V[wid] = lv; }
            __syncthreads();

            float vmax = W_V[0];
#pragma unroll
            for (int w = 1; w < 8; w++) vmax = fmaxf(vmax, W_V[w]);

            float es = __fadd_rn(expf(__fsub_rn(v0, vmax)),
                                 expf(__fsub_rn(v1, vmax)));
#pragma unroll
            for (int off = 16; off > 0; off >>= 1)
                es = __fadd_rn(es, __shfl_xor_sync(0xFFFFFFFFu, es, off));
            if ((tid & 31) == 0) W_E[wid] = es;
            __syncthreads();

            if (tid == 0) {
                float fs = W_S[0]; int fi = W_I[0];
                float S  = W_E[0];
#pragma unroll
                for (int w = 1; w < 8; w++) {
                    float os = W_S[w]; int oi = W_I[w];
                    if (os > fs || (os == fs && oi < fi)) { fs = os; fi = oi; }
                    S = __fadd_rn(S, W_E[w]);
                }
                int idx = fi;
                float vsel = __ldcg(&g_logits[(size_t)b * NN + idx]);  // idx is available
                float ps = __fdiv_rn(expf(__fsub_rn(vsel, vmax)), S);
                float lp = __fadd_rn(g_lp[b], logf(__fadd_rn(ps, 1e-9f)));
                g_lp[b]  = lp;
                g_sel[b] = idx;
                g_avail[b * 16 + (idx >> 5)] &= ~(1u << (idx & 31));
                out[(size_t)b * NN * NN + (size_t)t * NN + idx] = 1.0f;
                if (t == NN - 1) out[(size_t)BB * NN * NN + b] = lp;
            }
        }
        gsync();
    }
}

// -------- host launcher: 2 graph nodes (memset + persistent kernel) --------
extern "C" void kernel_launch(void* const* d_in, const int* in_sizes, int n_in,
                              void* d_out, int out_size)
{
    int base = (n_in == 11) ? 1 : 0;   // batch_size scalar first per metadata
    const float* Wih0 = (const float*)d_in[base + 0];
    const float* Whh0 = (const float*)d_in[base + 1];
    const float* bih0 = (const float*)d_in[base + 2];
    const float* bhh0 = (const float*)d_in[base + 3];
    const float* Wih1 = (const float*)d_in[base + 4];
    const float* Whh1 = (const float*)d_in[base + 5];
    const float* bih1 = (const float*)d_in[base + 6];
    const float* bhh1 = (const float*)d_in[base + 7];
    const float* Wout = (const float*)d_in[base + 8];
    const float* bout = (const float*)d_in[base + 9];
    float* out = (float*)d_out;
    (void)in_sizes;

    cudaMemsetAsync(d_out, 0, (size_t)out_size * sizeof(float), 0);
    perm_persistent<<<GBLK, NTHR>>>(Wih0, Whh0, bih0, bhh0,
                                    Wih1, Whh1, bih1, bhh1,
                                    Wout, bout, out);
}

// round 10
// speedup vs baseline: 2.3044x; 2.3044x over previous
#include <cuda_runtime.h>
#include <cstdint>
#include <cstddef>

// Fixed shapes: n=512, H=512, B=256
#define BB 256
#define HH 512
#define NN 512
#define GBLK 128      // persistent blocks: 4 batch tiles (64 rows) x 32 col tiles (16 cols)
#define NTHR 256
#define KT  32        // k-tile
#define SAX 66        // act smem stride [k][row], rows 64 + pad
#define SWX 20        // weight smem stride [k][col], cols 16 + pad (16B-aligned rows)
#define NEG_INF (-1.0e9f)
#define F32_TINY 1.17549435e-38f

// -------- device scratch (no allocations allowed) --------
__device__ float    g_h0[2][BB * HH];
__device__ float    g_h1[2][BB * HH];
__device__ float    g_logits[BB * NN];
__device__ int      g_sel[BB];
__device__ unsigned g_avail[BB * (NN / 32)];
__device__ float    g_lp[BB];
__device__ float    g_rowsum[3 * HH];
__device__ unsigned g_bar_cnt;
__device__ unsigned g_bar_gen;

// -------- Threefry-2x32 (20 rounds), bit-exact JAX replica --------
__device__ __forceinline__ unsigned rotl32(unsigned v, int r) {
    return (v << r) | (v >> (32 - r));
}

__device__ __forceinline__ void tf2x32(unsigned ks0, unsigned ks1,
                                       unsigned x0, unsigned x1,
                                       unsigned& o0, unsigned& o1)
{
    unsigned ks2 = ks0 ^ ks1 ^ 0x1BD11BDAu;
    x0 += ks0; x1 += ks1;
#define TF_R4(a,b,c,d) \
    x0 += x1; x1 = rotl32(x1,(a)); x1 ^= x0; \
    x0 += x1; x1 = rotl32(x1,(b)); x1 ^= x0; \
    x0 += x1; x1 = rotl32(x1,(c)); x1 ^= x0; \
    x0 += x1; x1 = rotl32(x1,(d)); x1 ^= x0;
    TF_R4(13,15,26,6)   x0 += ks1; x1 += ks2 + 1u;
    TF_R4(17,29,16,24)  x0 += ks2; x1 += ks0 + 2u;
    TF_R4(13,15,26,6)   x0 += ks0; x1 += ks1 + 3u;
    TF_R4(17,29,16,24)  x0 += ks1; x1 += ks2 + 4u;
    TF_R4(13,15,26,6)   x0 += ks2; x1 += ks0 + 5u;
#undef TF_R4
    o0 = x0; o1 = x1;
}

// XLA lowers logistic(x) as 0.5 + 0.5*tanh(0.5*x); mirror that op graph.
__device__ __forceinline__ float jax_sigmoid(float x) {
    return __fadd_rn(0.5f, __fmul_rn(0.5f, tanhf(__fmul_rn(0.5f, x))));
}

// L2-coherent float4 load (persistent kernel: L1 may hold stale lines)
__device__ __forceinline__ float4 ldcg4(const float* p) {
    return __ldcg(reinterpret_cast<const float4*>(p));
}
__device__ __forceinline__ float4 ldg4(const float* p) {
    return __ldg(reinterpret_cast<const float4*>(p));
}
__device__ __forceinline__ float f4c(float4 v, int i) {
    return i == 0 ? v.x : i == 1 ? v.y : i == 2 ? v.z : v.w;
}

// -------- packed f32x2 FMA: two IEEE fp32 FMAs per instruction --------
union f2u { float2 f; unsigned long long u; };

__device__ __forceinline__ float2 ffma2(float2 a, float2 b, float2 c) {
    f2u A, B, C, D;
    A.f = a; B.f = b; C.f = c;
    asm("fma.rn.f32x2 %0, %1, %2, %3;" : "=l"(D.u) : "l"(A.u), "l"(B.u), "l"(C.u));
    return D.f;
}
__device__ __forceinline__ float2 bc2(float a) { return make_float2(a, a); }

// -------- software grid barrier (all GBLK blocks resident) --------
__device__ __forceinline__ void gsync() {
    __syncthreads();
    if (threadIdx.x == 0) {
        __threadfence();
        unsigned gen = *(volatile unsigned*)&g_bar_gen;
        if (atomicAdd(&g_bar_cnt, 1u) == GBLK - 1u) {
            atomicExch(&g_bar_cnt, 0u);
            __threadfence();
            atomicAdd(&g_bar_gen, 1u);
        } else {
            while (*(volatile unsigned*)&g_bar_gen == gen) { }
        }
        __threadfence();
    }
    __syncthreads();
}

// smem layout (floats): AX[2112] AH[2112] WB[6][640]  => 8064 floats = 32.25 KB
#define AXp (SM)
#define AHp (SM + 2112)
#define WBp(g) (SM + 4224 + (g) * 640)

__global__ void __launch_bounds__(NTHR, 1) perm_persistent(
    const float* __restrict__ Wih0, const float* __restrict__ Whh0,
    const float* __restrict__ bih0, const float* __restrict__ bhh0,
    const float* __restrict__ Wih1, const float* __restrict__ Whh1,
    const float* __restrict__ bih1, const float* __restrict__ bhh1,
    const float* __restrict__ Wout, const float* __restrict__ bout,
    float* __restrict__ out)
{
    __shared__ __align__(16) float SM[8064];

    const int blk = blockIdx.x;
    const int tid = threadIdx.x;

    // ---------------- init (per-launch state reset) ----------------
    {
        for (int i = blk * NTHR + tid; i < BB * HH; i += GBLK * NTHR) {
            g_h0[0][i] = 0.0f;
            g_h1[0][i] = 0.0f;
        }
        if (tid < 2) g_lp[2 * blk + tid] = 0.0f;
        if (tid < 32) g_avail[(2 * blk + (tid >> 4)) * 16 + (tid & 15)] = 0xFFFFFFFFu;
        int lane = tid & 31;
        for (int row = blk * 8 + (tid >> 5); row < 3 * HH; row += GBLK * 8) {
            const float* rp = Wih0 + (size_t)row * HH;
            float s = 0.0f;
            for (int k = lane; k < HH; k += 32) s = __fadd_rn(s, rp[k]);
#pragma unroll
            for (int off = 16; off > 0; off >>= 1)
                s = __fadd_rn(s, __shfl_xor_sync(0xFFFFFFFFu, s, off));
            if (lane == 0) g_rowsum[row] = s;
        }
    }
    gsync();

    // tiles: blk = jy*32 + jx; jy 0..3 (64 batch rows), jx 0..31 (16 cols)
    const int jy = blk >> 5, jx = blk & 31;
    const int bm0 = jy * 64, jn0 = jx * 16;
    const bool isload = (tid >= 128);
    const int ltid = tid & 127;
    // compute-thread mapping (tid < 128): 2 rows x 4 cols
    const int cg = tid & 3;          // col group: cols jn0 + 4cg .. +3
    const int rg = tid >> 2;         // rows bm0 + 2rg, 2rg+1   (rg 0..31)
    // loader mappings (ltid 0..127)
    const int wj  = ltid & 15;               // weight col within tile
    const int wk  = (ltid >> 4) << 2;        // weight k offset {0,4,...,28}
    const int lrow = ltid >> 1;              // act row within tile (0..63)
    const int lks  = (ltid & 1) << 2;        // act k sub-offset {0,4}

    for (int t = 0; t < NN; t++) {
        const int p = t & 1;
        const float* h0_in  = g_h0[p];
        float*       h0_out = g_h0[p ^ 1];
        const float* h1_in  = g_h1[p];
        float*       h1_out = g_h1[p ^ 1];

        // ================= layer 0: h0n = GRU(onehot(sel), h0) =================
        {
            float gi[3][2][4];               // gather (compute threads only)
            float2 acc[3][2][2];             // [gate][row][half]
            float4 wr[3], ar[4];

            if (!isload) {
#pragma unroll
                for (int g = 0; g < 3; g++)
#pragma unroll
                    for (int mi = 0; mi < 2; mi++)
#pragma unroll
                        for (int h = 0; h < 2; h++) acc[g][mi][h] = make_float2(0.f, 0.f);
                if (t == 0) {
#pragma unroll
                    for (int g = 0; g < 3; g++)
#pragma unroll
                        for (int c = 0; c < 4; c++) {
                            float v = __ldcg(&g_rowsum[g * HH + jn0 + 4 * cg + c]);
                            gi[g][0][c] = v; gi[g][1][c] = v;
                        }
                } else {
#pragma unroll
                    for (int mi = 0; mi < 2; mi++) {
                        int xs = __ldcg(&g_sel[bm0 + 2 * rg + mi]);
#pragma unroll
                        for (int g = 0; g < 3; g++)
#pragma unroll
                            for (int c = 0; c < 4; c++)
                                gi[g][mi][c] = __ldg(&Wih0[(size_t)(g * HH + jn0 + 4 * cg + c) * HH + xs]);
                    }
                }
            } else {
#pragma unroll
                for (int g = 0; g < 3; g++)
                    wr[g] = ldg4(Whh0 + (size_t)(g * HH + jn0 + wj) * HH + wk);
#pragma unroll
                for (int q = 0; q < 4; q++)
                    ar[q] = ldcg4(h0_in + (size_t)(bm0 + lrow) * HH + lks + 8 * q);
            }

#pragma unroll 1
            for (int k0 = 0; k0 < HH; k0 += KT) {
                if (isload) {
#pragma unroll
                    for (int g = 0; g < 3; g++)
#pragma unroll
                        for (int i = 0; i < 4; i++)
                            WBp(g)[(wk + i) * SWX + wj] = f4c(wr[g], i);
#pragma unroll
                    for (int q = 0; q < 4; q++)
#pragma unroll
                        for (int i = 0; i < 4; i++)
                            AXp[(lks + 8 * q + i) * SAX + lrow] = f4c(ar[q], i);
                }
                __syncthreads();
                if (isload) {
                    if (k0 + KT < HH) {
                        int kn = k0 + KT;
#pragma unroll
                        for (int g = 0; g < 3; g++)
                            wr[g] = ldg4(Whh0 + (size_t)(g * HH + jn0 + wj) * HH + kn + wk);
#pragma unroll
                        for (int q = 0; q < 4; q++)
                            ar[q] = ldcg4(h0_in + (size_t)(bm0 + lrow) * HH + kn + lks + 8 * q);
                    }
                } else {
#pragma unroll
                    for (int k = 0; k < KT; k++) {
                        float2 xa = *reinterpret_cast<const float2*>(AXp + k * SAX + 2 * rg);
                        float2 x0 = bc2(xa.x), x1 = bc2(xa.y);
#pragma unroll
                        for (int g = 0; g < 3; g++) {
                            float4 w = *reinterpret_cast<const float4*>(WBp(g) + k * SWX + 4 * cg);
                            float2 wlo = make_float2(w.x, w.y), whi = make_float2(w.z, w.w);
                            acc[g][0][0] = ffma2(x0, wlo, acc[g][0][0]);
                            acc[g][0][1] = ffma2(x0, whi, acc[g][0][1]);
                            acc[g][1][0] = ffma2(x1, wlo, acc[g][1][0]);
                            acc[g][1][1] = ffma2(x1, whi, acc[g][1][1]);
                        }
                    }
                }
                __syncthreads();
            }

            if (!isload) {
                float4 bi0 = ldg4(bih0 + jn0 + 4 * cg);
                float4 bi1 = ldg4(bih0 + HH + jn0 + 4 * cg);
                float4 bi2 = ldg4(bih0 + 2 * HH + jn0 + 4 * cg);
                float4 bh0 = ldg4(bhh0 + jn0 + 4 * cg);
                float4 bh1 = ldg4(bhh0 + HH + jn0 + 4 * cg);
                float4 bh2 = ldg4(bhh0 + 2 * HH + jn0 + 4 * cg);
#pragma unroll
                for (int mi = 0; mi < 2; mi++) {
                    int b = bm0 + 2 * rg + mi;
                    float4 hp4 = ldcg4(h0_in + (size_t)b * HH + jn0 + 4 * cg);
                    float res[4];
#pragma unroll
                    for (int c = 0; c < 4; c++) {
                        float ar_ = (c & 1) ? acc[0][mi][c >> 1].y : acc[0][mi][c >> 1].x;
                        float az_ = (c & 1) ? acc[1][mi][c >> 1].y : acc[1][mi][c >> 1].x;
                        float an_ = (c & 1) ? acc[2][mi][c >> 1].y : acc[2][mi][c >> 1].x;
                        float ir  = __fadd_rn(gi[0][mi][c], f4c(bi0, c));
                        float iz  = __fadd_rn(gi[1][mi][c], f4c(bi1, c));
                        float inn = __fadd_rn(gi[2][mi][c], f4c(bi2, c));
                        float hr  = __fadd_rn(ar_, f4c(bh0, c));
                        float hz  = __fadd_rn(az_, f4c(bh1, c));
                        float hn  = __fadd_rn(an_, f4c(bh2, c));
                        float r  = jax_sigmoid(__fadd_rn(ir, hr));
                        float z  = jax_sigmoid(__fadd_rn(iz, hz));
                        float ng = tanhf(__fadd_rn(inn, __fmul_rn(r, hn)));
                        float hp = f4c(hp4, c);
                        res[c] = __fadd_rn(__fmul_rn(__fsub_rn(1.0f, z), ng), __fmul_rn(z, hp));
                    }
                    *reinterpret_cast<float4*>(h0_out + (size_t)b * HH + jn0 + 4 * cg) =
                        make_float4(res[0], res[1], res[2], res[3]);
                }
            }
        }
        gsync();

        // ================= layer 1: h1n = GRU(h0n, h1) =================
        {
            float2 accI[3][2][2], accH[3][2][2];
            float4 wr[6], ax[4], ah[4];

            if (!isload) {
#pragma unroll
                for (int g = 0; g < 3; g++)
#pragma unroll
                    for (int mi = 0; mi < 2; mi++)
#pragma unroll
                        for (int h = 0; h < 2; h++) {
                            accI[g][mi][h] = make_float2(0.f, 0.f);
                            accH[g][mi][h] = make_float2(0.f, 0.f);
                        }
            } else {
#pragma unroll
                for (int g = 0; g < 3; g++) {
                    wr[g]     = ldg4(Wih1 + (size_t)(g * HH + jn0 + wj) * HH + wk);
                    wr[3 + g] = ldg4(Whh1 + (size_t)(g * HH + jn0 + wj) * HH + wk);
                }
#pragma unroll
                for (int q = 0; q < 4; q++) {
                    ax[q] = ldcg4(h0_out + (size_t)(bm0 + lrow) * HH + lks + 8 * q);
                    ah[q] = ldcg4(h1_in  + (size_t)(bm0 + lrow) * HH + lks + 8 * q);
                }
            }

#pragma unroll 1
            for (int k0 = 0; k0 < HH; k0 += KT) {
                if (isload) {
#pragma unroll
                    for (int g = 0; g < 6; g++)
#pragma unroll
                        for (int i = 0; i < 4; i++)
                            WBp(g)[(wk + i) * SWX + wj] = f4c(wr[g], i);
#pragma unroll
                    for (int q = 0; q < 4; q++)
#pragma unroll
                        for (int i = 0; i < 4; i++) {
                            AXp[(lks + 8 * q + i) * SAX + lrow] = f4c(ax[q], i);
                            AHp[(lks + 8 * q + i) * SAX + lrow] = f4c(ah[q], i);
                        }
                }
                __syncthreads();
                if (isload) {
                    if (k0 + KT < HH) {
                        int kn = k0 + KT;
#pragma unroll
                        for (int g = 0; g < 3; g++) {
                            wr[g]     = ldg4(Wih1 + (size_t)(g * HH + jn0 + wj) * HH + kn + wk);
                            wr[3 + g] = ldg4(Whh1 + (size_t)(g * HH + jn0 + wj) * HH + kn + wk);
                        }
#pragma unroll
                        for (int q = 0; q < 4; q++) {
                            ax[q] = ldcg4(h0_out + (size_t)(bm0 + lrow) * HH + kn + lks + 8 * q);
                            ah[q] = ldcg4(h1_in  + (size_t)(bm0 + lrow) * HH + kn + lks + 8 * q);
                        }
                    }
                } else {
#pragma unroll
                    for (int k = 0; k < KT; k++) {
                        float2 xa = *reinterpret_cast<const float2*>(AXp + k * SAX + 2 * rg);
                        float2 ha = *reinterpret_cast<const float2*>(AHp + k * SAX + 2 * rg);
                        float2 x0 = bc2(xa.x), x1 = bc2(xa.y);
                        float2 h0b = bc2(ha.x), h1b = bc2(ha.y);
#pragma unroll
                        for (int g = 0; g < 3; g++) {
                            float4 wI = *reinterpret_cast<const float4*>(WBp(g) + k * SWX + 4 * cg);
                            float2 ilo = make_float2(wI.x, wI.y), ihi = make_float2(wI.z, wI.w);
                            accI[g][0][0] = ffma2(x0, ilo, accI[g][0][0]);
                            accI[g][0][1] = ffma2(x0, ihi, accI[g][0][1]);
                            accI[g][1][0] = ffma2(x1, ilo, accI[g][1][0]);
                            accI[g][1][1] = ffma2(x1, ihi, accI[g][1][1]);
                            float4 wH = *reinterpret_cast<const float4*>(WBp(3 + g) + k * SWX + 4 * cg);
                            float2 hlo = make_float2(wH.x, wH.y), hhi = make_float2(wH.z, wH.w);
                            accH[g][0][0] = ffma2(h0b, hlo, accH[g][0][0]);
                            accH[g][0][1] = ffma2(h0b, hhi, accH[g][0][1]);
                            accH[g][1][0] = ffma2(h1b, hlo, accH[g][1][0]);
                            accH[g][1][1] = ffma2(h1b, hhi, accH[g][1][1]);
                        }
                    }
                }
                __syncthreads();
            }

            if (!isload) {
                float4 bi0 = ldg4(bih1 + jn0 + 4 * cg);
                float4 bi1 = ldg4(bih1 + HH + jn0 + 4 * cg);
                float4 bi2 = ldg4(bih1 + 2 * HH + jn0 + 4 * cg);
                float4 bh0 = ldg4(bhh1 + jn0 + 4 * cg);
                float4 bh1 = ldg4(bhh1 + HH + jn0 + 4 * cg);
                float4 bh2 = ldg4(bhh1 + 2 * HH + jn0 + 4 * cg);
#pragma unroll
                for (int mi = 0; mi < 2; mi++) {
                    int b = bm0 + 2 * rg + mi;
                    float4 hp4 = ldcg4(h1_in + (size_t)b * HH + jn0 + 4 * cg);
                    float res[4];
#pragma unroll
                    for (int c = 0; c < 4; c++) {
                        float aIr = (c & 1) ? accI[0][mi][c >> 1].y : accI[0][mi][c >> 1].x;
                        float aIz = (c & 1) ? accI[1][mi][c >> 1].y : accI[1][mi][c >> 1].x;
                        float aIn = (c & 1) ? accI[2][mi][c >> 1].y : accI[2][mi][c >> 1].x;
                        float aHr = (c & 1) ? accH[0][mi][c >> 1].y : accH[0][mi][c >> 1].x;
                        float aHz = (c & 1) ? accH[1][mi][c >> 1].y : accH[1][mi][c >> 1].x;
                        float aHn = (c & 1) ? accH[2][mi][c >> 1].y : accH[2][mi][c >> 1].x;
                        float ir  = __fadd_rn(aIr, f4c(bi0, c));
                        float iz  = __fadd_rn(aIz, f4c(bi1, c));
                        float inn = __fadd_rn(aIn, f4c(bi2, c));
                        float hr  = __fadd_rn(aHr, f4c(bh0, c));
                        float hz  = __fadd_rn(aHz, f4c(bh1, c));
                        float hn  = __fadd_rn(aHn, f4c(bh2, c));
                        float r  = jax_sigmoid(__fadd_rn(ir, hr));
                        float z  = jax_sigmoid(__fadd_rn(iz, hz));
                        float ng = tanhf(__fadd_rn(inn, __fmul_rn(r, hn)));
                        float hp = f4c(hp4, c);
                        res[c] = __fadd_rn(__fmul_rn(__fsub_rn(1.0f, z), ng), __fmul_rn(z, hp));
                    }
                    *reinterpret_cast<float4*>(h1_out + (size_t)b * HH + jn0 + 4 * cg) =
                        make_float4(res[0], res[1], res[2], res[3]);
                }
            }
        }
        gsync();

        // ================= logits = h1n @ W_out^T + b_out =================
        {
            float2 acc[2][2];
            float4 wr0, ar[4];
            if (!isload) {
#pragma unroll
                for (int mi = 0; mi < 2; mi++)
#pragma unroll
                    for (int h = 0; h < 2; h++) acc[mi][h] = make_float2(0.f, 0.f);
            } else {
                wr0 = ldg4(Wout + (size_t)(jn0 + wj) * HH + wk);
#pragma unroll
                for (int q = 0; q < 4; q++)
                    ar[q] = ldcg4(h1_out + (size_t)(bm0 + lrow) * HH + lks + 8 * q);
            }
#pragma unroll 1
            for (int k0 = 0; k0 < HH; k0 += KT) {
                if (isload) {
#pragma unroll
                    for (int i = 0; i < 4; i++)
                        WBp(0)[(wk + i) * SWX + wj] = f4c(wr0, i);
#pragma unroll
                    for (int q = 0; q < 4; q++)
#pragma unroll
                        for (int i = 0; i < 4; i++)
                            AXp[(lks + 8 * q + i) * SAX + lrow] = f4c(ar[q], i);
                }
                __syncthreads();
                if (isload) {
                    if (k0 + KT < HH) {
                        int kn = k0 + KT;
                        wr0 = ldg4(Wout + (size_t)(jn0 + wj) * HH + kn + wk);
#pragma unroll
                        for (int q = 0; q < 4; q++)
                            ar[q] = ldcg4(h1_out + (size_t)(bm0 + lrow) * HH + kn + lks + 8 * q);
                    }
                } else {
#pragma unroll
                    for (int k = 0; k < KT; k++) {
                        float2 xa = *reinterpret_cast<const float2*>(AXp + k * SAX + 2 * rg);
                        float4 w = *reinterpret_cast<const float4*>(WBp(0) + k * SWX + 4 * cg);
                        float2 wlo = make_float2(w.x, w.y), whi = make_float2(w.z, w.w);
                        float2 x0 = bc2(xa.x), x1 = bc2(xa.y);
                        acc[0][0] = ffma2(x0, wlo, acc[0][0]);
                        acc[0][1] = ffma2(x0, whi, acc[0][1]);
                        acc[1][0] = ffma2(x1, wlo, acc[1][0]);
                        acc[1][1] = ffma2(x1, whi, acc[1][1]);
                    }
                }
                __syncthreads();
            }
            if (!isload) {
                float4 bo = ldg4(bout + jn0 + 4 * cg);
#pragma unroll
                for (int mi = 0; mi < 2; mi++) {
                    int b = bm0 + 2 * rg + mi;
                    float res[4];
#pragma unroll
                    for (int c = 0; c < 4; c++) {
                        float a = (c & 1) ? acc[mi][c >> 1].y : acc[mi][c >> 1].x;
                        res[c] = __fadd_rn(a, f4c(bo, c));
                    }
                    *reinterpret_cast<float4*>(g_logits + (size_t)b * NN + jn0 + 4 * cg) =
                        make_float4(res[0], res[1], res[2], res[3]);
                }
            }
        }
        gsync();

        // ===== sample: 2 batch rows per block (128 threads each), shuffle reductions =====
        {
            float* SSv = SM;                  // [2][4]
            int*   SSi = (int*)(SM + 8);      // [2][4]
            float* SVm = SM + 16;             // [2][4]
            float* SEx = SM + 24;             // [2][4]

            const int r   = tid >> 7;         // row within block pair
            const int c0  = tid & 127;
            const int wir = (tid >> 5) & 3;   // warp within row
            const int b   = 2 * blk + r;

            unsigned sk0, sk1;
            tf2x32(0u, 42u, 0u, (unsigned)t, sk0, sk1);

            float vq[4];
            float bs = -3.4e38f; int bi = 0;
            float lv = -3.4e38f;
#pragma unroll
            for (int q = 0; q < 4; q++) {
                int col = c0 + 128 * q;
                float lg = __ldcg(&g_logits[(size_t)b * NN + col]);
                unsigned w = g_avail[b * 16 + (col >> 5)];
                float v = ((w >> (col & 31)) & 1u) ? lg : NEG_INF;
                vq[q] = v;
                unsigned o0, o1;
                tf2x32(sk0, sk1, 0u, (unsigned)(b * NN + col), o0, o1);
                unsigned bits = o0 ^ o1;
                float f = __fsub_rn(__uint_as_float((bits >> 9) | 0x3F800000u), 1.0f);
                float gmb = -logf(-logf(fmaxf(f, F32_TINY)));
                float s = __fadd_rn(gmb, v);
                if (s > bs || (s == bs && col < bi)) { bs = s; bi = col; }
                lv = fmaxf(lv, v);
            }
#pragma unroll
            for (int off = 16; off > 0; off >>= 1) {
                float os = __shfl_xor_sync(0xFFFFFFFFu, bs, off);
                int   oi = __shfl_xor_sync(0xFFFFFFFFu, bi, off);
                float ov = __shfl_xor_sync(0xFFFFFFFFu, lv, off);
                if (os > bs || (os == bs && oi < bi)) { bs = os; bi = oi; }
                lv = fmaxf(lv, ov);
            }
            if ((tid & 31) == 0) {
                SSv[r * 4 + wir] = bs; SSi[r * 4 + wir] = bi; SVm[r * 4 + wir] = lv;
            }
            __syncthreads();

            float vmax = SVm[r * 4];
#pragma unroll
            for (int w = 1; w < 4; w++) vmax = fmaxf(vmax, SVm[r * 4 + w]);

            float es = 0.0f;
#pragma unroll
            for (int q = 0; q < 4; q++)
                es = __fadd_rn(es, expf(__fsub_rn(vq[q], vmax)));
#pragma unroll
            for (int off = 16; off > 0; off >>= 1)
                es = __fadd_rn(es, __shfl_xor_sync(0xFFFFFFFFu, es, off));
            if ((tid & 31) == 0) SEx[r * 4 + wir] = es;
            __syncthreads();

            if (c0 == 0) {
                float fs = SSv[r * 4]; int fi = SSi[r * 4];
                float S  = SEx[r * 4];
#pragma unroll
                for (int w = 1; w < 4; w++) {
                    float os = SSv[r * 4 + w]; int oi = SSi[r * 4 + w];
                    if (os > fs || (os == fs && oi < fi)) { fs = os; fi = oi; }
                    S = __fadd_rn(S, SEx[r * 4 + w]);
                }
                int idx = fi;
                float vsel = __ldcg(&g_logits[(size_t)b * NN + idx]);   // idx is available
                float ps = __fdiv_rn(expf(__fsub_rn(vsel, vmax)), S);
                float lp = __fadd_rn(g_lp[b], logf(__fadd_rn(ps, 1e-9f)));
                g_lp[b]  = lp;
                g_sel[b] = idx;
                g_avail[b * 16 + (idx >> 5)] &= ~(1u << (idx & 31));
                out[(size_t)b * NN * NN + (size_t)t * NN + idx] = 1.0f;
                if (t == NN - 1) out[(size_t)BB * NN * NN + b] = lp;
            }
        }
        gsync();
    }
}

// -------- host launcher: 2 graph nodes (memset + persistent kernel) --------
extern "C" void kernel_launch(void* const* d_in, const int* in_sizes, int n_in,
                              void* d_out, int out_size)
{
    int base = (n_in == 11) ? 1 : 0;   // batch_size scalar first per metadata
    const float* Wih0 = (const float*)d_in[base + 0];
    const float* Whh0 = (const float*)d_in[base + 1];
    const float* bih0 = (const float*)d_in[base + 2];
    const float* bhh0 = (const float*)d_in[base + 3];
    const float* Wih1 = (const float*)d_in[base + 4];
    const float* Whh1 = (const float*)d_in[base + 5];
    const float* bih1 = (const float*)d_in[base + 6];
    const float* bhh1 = (const float*)d_in[base + 7];
    const float* Wout = (const float*)d_in[base + 8];
    const float* bout = (const float*)d_in[base + 9];
    float* out = (float*)d_out;
    (void)in_sizes;

    cudaMemsetAsync(d_out, 0, (size_t)out_size * sizeof(float), 0);
    perm_persistent<<<GBLK, NTHR>>>(Wih0, Whh0, bih0, bhh0,
                                    Wih1, Whh1, bih1, bhh1,
                                    Wout, bout, out);
}

// round 11
// speedup vs baseline: 2.7485x; 1.1927x over previous
#include <cuda_runtime.h>
#include <cstdint>
#include <cstddef>

// Fixed shapes: n=512, H=512, B=256
#define BB 256
#define HH 512
#define NN 512
#define GBLK 128      // persistent blocks: 8 batch tiles (32 rows) x 16 col tiles (32 cols)
#define NTHR 256
#define KT   32       // k per tile (16 kk pairs)
#define XS   68       // smem stride per kk (64 payload + 4 pad), multiple of 4
#define BUFF 1088     // floats per buffer (16 kk * XS)
#define SMEMF (2 * 8 * BUFF)   // 17408 floats = 69632 B
#define NEG_INF (-1.0e9f)
#define F32_TINY 1.17549435e-38f

// -------- device scratch (no allocations allowed) --------
__device__ float    g_h0[2][BB * HH];
__device__ float    g_h1[2][BB * HH];
__device__ float    g_logits[BB * NN];
__device__ int      g_sel[BB];
__device__ unsigned g_avail[BB * (NN / 32)];
__device__ float    g_lp[BB];
__device__ float    g_rowsum[3 * HH];
__device__ unsigned g_bar_cnt;
__device__ unsigned g_bar_gen;

// -------- Threefry-2x32 (20 rounds), bit-exact JAX replica --------
__device__ __forceinline__ unsigned rotl32(unsigned v, int r) {
    return (v << r) | (v >> (32 - r));
}

__device__ __forceinline__ void tf2x32(unsigned ks0, unsigned ks1,
                                       unsigned x0, unsigned x1,
                                       unsigned& o0, unsigned& o1)
{
    unsigned ks2 = ks0 ^ ks1 ^ 0x1BD11BDAu;
    x0 += ks0; x1 += ks1;
#define TF_R4(a,b,c,d) \
    x0 += x1; x1 = rotl32(x1,(a)); x1 ^= x0; \
    x0 += x1; x1 = rotl32(x1,(b)); x1 ^= x0; \
    x0 += x1; x1 = rotl32(x1,(c)); x1 ^= x0; \
    x0 += x1; x1 = rotl32(x1,(d)); x1 ^= x0;
    TF_R4(13,15,26,6)   x0 += ks1; x1 += ks2 + 1u;
    TF_R4(17,29,16,24)  x0 += ks2; x1 += ks0 + 2u;
    TF_R4(13,15,26,6)   x0 += ks0; x1 += ks1 + 3u;
    TF_R4(17,29,16,24)  x0 += ks1; x1 += ks2 + 4u;
    TF_R4(13,15,26,6)   x0 += ks2; x1 += ks0 + 5u;
#undef TF_R4
    o0 = x0; o1 = x1;
}

// XLA lowers logistic(x) as 0.5 + 0.5*tanh(0.5*x); mirror that op graph.
__device__ __forceinline__ float jax_sigmoid(float x) {
    return __fadd_rn(0.5f, __fmul_rn(0.5f, tanhf(__fmul_rn(0.5f, x))));
}

// L2-coherent float4 load (persistent kernel: L1 may hold stale lines)
__device__ __forceinline__ float4 ldcg4(const float* p) {
    return __ldcg(reinterpret_cast<const float4*>(p));
}
__device__ __forceinline__ float4 ldg4(const float* p) {
    return __ldg(reinterpret_cast<const float4*>(p));
}

// -------- packed f32x2 FMA: two IEEE fp32 FMAs per instruction --------
union f2u { float2 f; unsigned long long u; };

__device__ __forceinline__ float2 ffma2(float2 a, float2 b, float2 c) {
    f2u A, B, C, D;
    A.f = a; B.f = b; C.f = c;
    asm("fma.rn.f32x2 %0, %1, %2, %3;" : "=l"(D.u) : "l"(A.u), "l"(B.u), "l"(C.u));
    return D.f;
}
__device__ __forceinline__ float2 bc2(float a) { return make_float2(a, a); }

// paired-k transposed store: gmem float4 (4 consecutive k of one row/col)
// -> two float2 into kk and kk+1 planes at element slot e (= row or col).
__device__ __forceinline__ void st_pair(float* buf, int lc, int e, float4 v) {
    int kk = lc >> 1;   // lc multiple of 4 -> kk even
    *reinterpret_cast<float2*>(buf + kk * XS + e * 2)       = make_float2(v.x, v.y);
    *reinterpret_cast<float2*>(buf + (kk + 1) * XS + e * 2) = make_float2(v.z, v.w);
}
__device__ __forceinline__ float4 ld4s(const float* p) {
    return *reinterpret_cast<const float4*>(p);
}

// -------- software grid barrier (all GBLK blocks resident) --------
__device__ __forceinline__ void gsync() {
    __syncthreads();
    if (threadIdx.x == 0) {
        __threadfence();
        unsigned gen = *(volatile unsigned*)&g_bar_gen;
        if (atomicAdd(&g_bar_cnt, 1u) == GBLK - 1u) {
            atomicExch(&g_bar_cnt, 0u);
            __threadfence();
            atomicAdd(&g_bar_gen, 1u);
        } else {
            while (*(volatile unsigned*)&g_bar_gen == gen) { }
        }
        __threadfence();
    }
    __syncthreads();
}

// stage s (0/1), buffer i (0..7)
#define BUFV(s, i) (SM + ((s) * 8 + (i)) * BUFF)

__global__ void __launch_bounds__(NTHR, 1) perm_persistent(
    const float* __restrict__ Wih0, const float* __restrict__ Whh0,
    const float* __restrict__ bih0, const float* __restrict__ bhh0,
    const float* __restrict__ Wih1, const float* __restrict__ Whh1,
    const float* __restrict__ bih1, const float* __restrict__ bhh1,
    const float* __restrict__ Wout, const float* __restrict__ bout,
    float* __restrict__ out)
{
    extern __shared__ float SM[];   // SMEMF floats (69.6 KB)

    const int blk = blockIdx.x;
    const int tid = threadIdx.x;

    // ---------------- init (per-launch state reset) ----------------
    {
        for (int i = blk * NTHR + tid; i < BB * HH; i += GBLK * NTHR) {
            g_h0[0][i] = 0.0f;
            g_h1[0][i] = 0.0f;
        }
        if (tid < 2) g_lp[2 * blk + tid] = 0.0f;
        if (tid < 32) g_avail[(2 * blk + (tid >> 4)) * 16 + (tid & 15)] = 0xFFFFFFFFu;
        int lane = tid & 31;
        for (int row = blk * 8 + (tid >> 5); row < 3 * HH; row += GBLK * 8) {
            const float* rp = Wih0 + (size_t)row * HH;
            float s = 0.0f;
            for (int k = lane; k < HH; k += 32) s = __fadd_rn(s, rp[k]);
#pragma unroll
            for (int off = 16; off > 0; off >>= 1)
                s = __fadd_rn(s, __shfl_xor_sync(0xFFFFFFFFu, s, off));
            if (lane == 0) g_rowsum[row] = s;
        }
    }
    gsync();

    // tile jobs: 8 batch tiles (32 rows) x 16 col tiles (32 cols)
    const int jx = blk & 15;
    const int jy = blk >> 4;
    const int bm0 = jy * 32;
    const int jn0 = jx * 32;
    const int tx = tid & 15, ty = tid >> 4;      // compute: rows 2ty,2ty+1 ; cols 2tx,2tx+1
    const int lr = tid >> 3, lc = (tid & 7) << 2; // loader: element lr, k-offset lc

    for (int t = 0; t < NN; t++) {
        const int p = t & 1;
        const float* h0_in  = g_h0[p];
        float*       h0_out = g_h0[p ^ 1];
        const float* h1_in  = g_h1[p];
        float*       h1_out = g_h1[p ^ 1];

        // ================ layer 0: h0n = GRU(onehot(sel), h0) ================
        {
            // hoisted input-gate gather (overlaps with GEMM)
            float gi[2][3][2];
            if (t == 0) {
#pragma unroll
                for (int ni = 0; ni < 2; ni++) {
                    int j = jn0 + 2 * tx + ni;
                    float r0 = __ldcg(&g_rowsum[j]);
                    float r1 = __ldcg(&g_rowsum[j + HH]);
                    float r2 = __ldcg(&g_rowsum[j + 2 * HH]);
#pragma unroll
                    for (int mi = 0; mi < 2; mi++) {
                        gi[mi][0][ni] = r0; gi[mi][1][ni] = r1; gi[mi][2][ni] = r2;
                    }
                }
            } else {
#pragma unroll
                for (int mi = 0; mi < 2; mi++) {
                    int xs = __ldcg(&g_sel[bm0 + 2 * ty + mi]);
#pragma unroll
                    for (int g = 0; g < 3; g++)
#pragma unroll
                        for (int ni = 0; ni < 2; ni++)
                            gi[mi][g][ni] = __ldg(&Wih0[(size_t)(g * HH + jn0 + 2 * tx + ni) * HH + xs]);
                }
            }

            float2 acc[3][2];  // [gate][row], lanes = (col 2tx, col 2tx+1)
#pragma unroll
            for (int g = 0; g < 3; g++) { acc[g][0] = make_float2(0.f,0.f); acc[g][1] = make_float2(0.f,0.f); }

            const float* asrc = h0_in + (size_t)(bm0 + lr) * HH + lc;
            const float* wsrc0 = Whh0 + (size_t)(jn0 + lr) * HH + lc;
            const float* wsrc1 = Whh0 + (size_t)(HH + jn0 + lr) * HH + lc;
            const float* wsrc2 = Whh0 + (size_t)(2 * HH + jn0 + lr) * HH + lc;

            float4 pa = ldcg4(asrc), p0 = ldg4(wsrc0), p1 = ldg4(wsrc1), p2 = ldg4(wsrc2);
            st_pair(BUFV(0,0), lc, lr, pa);
            st_pair(BUFV(0,1), lc, lr, p0);
            st_pair(BUFV(0,2), lc, lr, p1);
            st_pair(BUFV(0,3), lc, lr, p2);
            __syncthreads();

#pragma unroll 1
            for (int tl = 0; tl < 16; tl++) {
                const int cs = tl & 1;
                if (tl < 15) {
                    int kn = (tl + 1) * KT;
                    pa = ldcg4(asrc + kn); p0 = ldg4(wsrc0 + kn);
                    p1 = ldg4(wsrc1 + kn); p2 = ldg4(wsrc2 + kn);
                }
                const float* A = BUFV(cs, 0);
                const float* W0 = BUFV(cs, 1);
                const float* W1 = BUFV(cs, 2);
                const float* W2 = BUFV(cs, 3);
#pragma unroll
                for (int kk = 0; kk < 16; kk++) {
                    float4 xa = ld4s(A + kk * XS + 4 * ty);
                    {
                        float4 w = ld4s(W0 + kk * XS + 4 * tx);
                        float2 w0 = make_float2(w.x, w.z), w1 = make_float2(w.y, w.w);
                        acc[0][0] = ffma2(bc2(xa.x), w0, acc[0][0]);
                        acc[0][0] = ffma2(bc2(xa.y), w1, acc[0][0]);
                        acc[0][1] = ffma2(bc2(xa.z), w0, acc[0][1]);
                        acc[0][1] = ffma2(bc2(xa.w), w1, acc[0][1]);
                    }
                    {
                        float4 w = ld4s(W1 + kk * XS + 4 * tx);
                        float2 w0 = make_float2(w.x, w.z), w1 = make_float2(w.y, w.w);
                        acc[1][0] = ffma2(bc2(xa.x), w0, acc[1][0]);
                        acc[1][0] = ffma2(bc2(xa.y), w1, acc[1][0]);
                        acc[1][1] = ffma2(bc2(xa.z), w0, acc[1][1]);
                        acc[1][1] = ffma2(bc2(xa.w), w1, acc[1][1]);
                    }
                    {
                        float4 w = ld4s(W2 + kk * XS + 4 * tx);
                        float2 w0 = make_float2(w.x, w.z), w1 = make_float2(w.y, w.w);
                        acc[2][0] = ffma2(bc2(xa.x), w0, acc[2][0]);
                        acc[2][0] = ffma2(bc2(xa.y), w1, acc[2][0]);
                        acc[2][1] = ffma2(bc2(xa.z), w0, acc[2][1]);
                        acc[2][1] = ffma2(bc2(xa.w), w1, acc[2][1]);
                    }
                }
                if (tl < 15) {
                    const int ns = cs ^ 1;
                    st_pair(BUFV(ns,0), lc, lr, pa);
                    st_pair(BUFV(ns,1), lc, lr, p0);
                    st_pair(BUFV(ns,2), lc, lr, p1);
                    st_pair(BUFV(ns,3), lc, lr, p2);
                }
                __syncthreads();
            }

#pragma unroll
            for (int mi = 0; mi < 2; mi++) {
                int b = bm0 + 2 * ty + mi;
#pragma unroll
                for (int ni = 0; ni < 2; ni++) {
                    int j = jn0 + 2 * tx + ni;
                    float ir  = __fadd_rn(gi[mi][0][ni], bih0[j]);
                    float iz  = __fadd_rn(gi[mi][1][ni], bih0[j + HH]);
                    float inn = __fadd_rn(gi[mi][2][ni], bih0[j + 2 * HH]);
                    float hr = __fadd_rn(ni ? acc[0][mi].y : acc[0][mi].x, bhh0[j]);
                    float hz = __fadd_rn(ni ? acc[1][mi].y : acc[1][mi].x, bhh0[j + HH]);
                    float hn = __fadd_rn(ni ? acc[2][mi].y : acc[2][mi].x, bhh0[j + 2 * HH]);
                    float r  = jax_sigmoid(__fadd_rn(ir, hr));
                    float z  = jax_sigmoid(__fadd_rn(iz, hz));
                    float ng = tanhf(__fadd_rn(inn, __fmul_rn(r, hn)));
                    float hp = __ldcg(&h0_in[(size_t)b * HH + j]);
                    h0_out[(size_t)b * HH + j] =
                        __fadd_rn(__fmul_rn(__fsub_rn(1.0f, z), ng), __fmul_rn(z, hp));
                }
            }
        }
        gsync();

        // ================ layer 1: h1n = GRU(h0n, h1) ================
        {
            float2 accI[3][2], accH[3][2];
#pragma unroll
            for (int g = 0; g < 3; g++) {
                accI[g][0] = make_float2(0.f,0.f); accI[g][1] = make_float2(0.f,0.f);
                accH[g][0] = make_float2(0.f,0.f); accH[g][1] = make_float2(0.f,0.f);
            }
            const float* xsrc = h0_out + (size_t)(bm0 + lr) * HH + lc;
            const float* hsrc = h1_in  + (size_t)(bm0 + lr) * HH + lc;
            const float* wsrc[6];
#pragma unroll
            for (int g = 0; g < 3; g++) {
                wsrc[g]     = Wih1 + (size_t)(g * HH + jn0 + lr) * HH + lc;
                wsrc[3 + g] = Whh1 + (size_t)(g * HH + jn0 + lr) * HH + lc;
            }

            float4 px = ldcg4(xsrc), ph = ldcg4(hsrc);
            float4 pw[6];
#pragma unroll
            for (int g = 0; g < 6; g++) pw[g] = ldg4(wsrc[g]);
            st_pair(BUFV(0,0), lc, lr, px);
            st_pair(BUFV(0,1), lc, lr, ph);
#pragma unroll
            for (int g = 0; g < 6; g++) st_pair(BUFV(0, 2 + g), lc, lr, pw[g]);
            __syncthreads();

#pragma unroll 1
            for (int tl = 0; tl < 16; tl++) {
                const int cs = tl & 1;
                if (tl < 15) {
                    int kn = (tl + 1) * KT;
                    px = ldcg4(xsrc + kn); ph = ldcg4(hsrc + kn);
#pragma unroll
                    for (int g = 0; g < 6; g++) pw[g] = ldg4(wsrc[g] + kn);
                }
                const float* AX = BUFV(cs, 0);
                const float* AH = BUFV(cs, 1);
#pragma unroll
                for (int kk = 0; kk < 16; kk++) {
                    float4 xa = ld4s(AX + kk * XS + 4 * ty);
                    float4 ha = ld4s(AH + kk * XS + 4 * ty);
#pragma unroll
                    for (int g = 0; g < 3; g++) {
                        float4 wi = ld4s(BUFV(cs, 2 + g) + kk * XS + 4 * tx);
                        float2 wi0 = make_float2(wi.x, wi.z), wi1 = make_float2(wi.y, wi.w);
                        accI[g][0] = ffma2(bc2(xa.x), wi0, accI[g][0]);
                        accI[g][0] = ffma2(bc2(xa.y), wi1, accI[g][0]);
                        accI[g][1] = ffma2(bc2(xa.z), wi0, accI[g][1]);
                        accI[g][1] = ffma2(bc2(xa.w), wi1, accI[g][1]);
                        float4 wh = ld4s(BUFV(cs, 5 + g) + kk * XS + 4 * tx);
                        float2 wh0 = make_float2(wh.x, wh.z), wh1 = make_float2(wh.y, wh.w);
                        accH[g][0] = ffma2(bc2(ha.x), wh0, accH[g][0]);
                        accH[g][0] = ffma2(bc2(ha.y), wh1, accH[g][0]);
                        accH[g][1] = ffma2(bc2(ha.z), wh0, accH[g][1]);
                        accH[g][1] = ffma2(bc2(ha.w), wh1, accH[g][1]);
                    }
                }
                if (tl < 15) {
                    const int ns = cs ^ 1;
                    st_pair(BUFV(ns,0), lc, lr, px);
                    st_pair(BUFV(ns,1), lc, lr, ph);
#pragma unroll
                    for (int g = 0; g < 6; g++) st_pair(BUFV(ns, 2 + g), lc, lr, pw[g]);
                }
                __syncthreads();
            }

#pragma unroll
            for (int mi = 0; mi < 2; mi++) {
#pragma unroll
                for (int ni = 0; ni < 2; ni++) {
                    int b = bm0 + 2 * ty + mi;
                    int j = jn0 + 2 * tx + ni;
                    float ir  = __fadd_rn(ni ? accI[0][mi].y : accI[0][mi].x, bih1[j]);
                    float iz  = __fadd_rn(ni ? accI[1][mi].y : accI[1][mi].x, bih1[j + HH]);
                    float inn = __fadd_rn(ni ? accI[2][mi].y : accI[2][mi].x, bih1[j + 2 * HH]);
                    float hr  = __fadd_rn(ni ? accH[0][mi].y : accH[0][mi].x, bhh1[j]);
                    float hz  = __fadd_rn(ni ? accH[1][mi].y : accH[1][mi].x, bhh1[j + HH]);
                    float hn  = __fadd_rn(ni ? accH[2][mi].y : accH[2][mi].x, bhh1[j + 2 * HH]);
                    float r  = jax_sigmoid(__fadd_rn(ir, hr));
                    float z  = jax_sigmoid(__fadd_rn(iz, hz));
                    float ng = tanhf(__fadd_rn(inn, __fmul_rn(r, hn)));
                    float hp = __ldcg(&h1_in[(size_t)b * HH + j]);
                    h1_out[(size_t)b * HH + j] =
                        __fadd_rn(__fmul_rn(__fsub_rn(1.0f, z), ng), __fmul_rn(z, hp));
                }
            }
        }
        gsync();

        // ================ logits = h1n @ W_out^T + b_out ================
        {
            float2 acc[2];
            acc[0] = make_float2(0.f,0.f); acc[1] = make_float2(0.f,0.f);
            const float* asrc = h1_out + (size_t)(bm0 + lr) * HH + lc;
            const float* wsrc = Wout + (size_t)(jn0 + lr) * HH + lc;

            float4 pa = ldcg4(asrc), pb = ldg4(wsrc);
            st_pair(BUFV(0,0), lc, lr, pa);
            st_pair(BUFV(0,1), lc, lr, pb);
            __syncthreads();

#pragma unroll 1
            for (int tl = 0; tl < 16; tl++) {
                const int cs = tl & 1;
                if (tl < 15) {
                    int kn = (tl + 1) * KT;
                    pa = ldcg4(asrc + kn); pb = ldg4(wsrc + kn);
                }
                const float* A = BUFV(cs, 0);
                const float* W = BUFV(cs, 1);
#pragma unroll
                for (int kk = 0; kk < 16; kk++) {
                    float4 xa = ld4s(A + kk * XS + 4 * ty);
                    float4 w  = ld4s(W + kk * XS + 4 * tx);
                    float2 w0 = make_float2(w.x, w.z), w1 = make_float2(w.y, w.w);
                    acc[0] = ffma2(bc2(xa.x), w0, acc[0]);
                    acc[0] = ffma2(bc2(xa.y), w1, acc[0]);
                    acc[1] = ffma2(bc2(xa.z), w0, acc[1]);
                    acc[1] = ffma2(bc2(xa.w), w1, acc[1]);
                }
                if (tl < 15) {
                    const int ns = cs ^ 1;
                    st_pair(BUFV(ns,0), lc, lr, pa);
                    st_pair(BUFV(ns,1), lc, lr, pb);
                }
                __syncthreads();
            }
#pragma unroll
            for (int mi = 0; mi < 2; mi++)
#pragma unroll
                for (int ni = 0; ni < 2; ni++) {
                    int b = bm0 + 2 * ty + mi;
                    int c = jn0 + 2 * tx + ni;
                    g_logits[(size_t)b * NN + c] =
                        __fadd_rn(ni ? acc[mi].y : acc[mi].x, bout[c]);
                }
        }
        gsync();

        // ===== sample: 2 batch rows per block (128 threads each), shuffle reductions =====
        {
            float* SSv = SM;                  // [2][4]
            int*   SSi = (int*)(SM + 8);      // [2][4]
            float* SVm = SM + 16;             // [2][4]
            float* SEx = SM + 24;             // [2][4]

            const int r   = tid >> 7;
            const int c0  = tid & 127;
            const int wir = (tid >> 5) & 3;
            const int b   = 2 * blk + r;

            unsigned sk0, sk1;
            tf2x32(0u, 42u, 0u, (unsigned)t, sk0, sk1);

            float vq[4];
            float bs = -3.4e38f; int bi = 0;
            float lv = -3.4e38f;
#pragma unroll
            for (int q = 0; q < 4; q++) {
                int col = c0 + 128 * q;
                float lg = __ldcg(&g_logits[(size_t)b * NN + col]);
                unsigned w = g_avail[b * 16 + (col >> 5)];
                float v = ((w >> (col & 31)) & 1u) ? lg : NEG_INF;
                vq[q] = v;
                unsigned o0, o1;
                tf2x32(sk0, sk1, 0u, (unsigned)(b * NN + col), o0, o1);
                unsigned bits = o0 ^ o1;
                float f = __fsub_rn(__uint_as_float((bits >> 9) | 0x3F800000u), 1.0f);
                float gmb = -logf(-logf(fmaxf(f, F32_TINY)));
                float s = __fadd_rn(gmb, v);
                if (s > bs || (s == bs && col < bi)) { bs = s; bi = col; }
                lv = fmaxf(lv, v);
            }
#pragma unroll
            for (int off = 16; off > 0; off >>= 1) {
                float os = __shfl_xor_sync(0xFFFFFFFFu, bs, off);
                int   oi = __shfl_xor_sync(0xFFFFFFFFu, bi, off);
                float ov = __shfl_xor_sync(0xFFFFFFFFu, lv, off);
                if (os > bs || (os == bs && oi < bi)) { bs = os; bi = oi; }
                lv = fmaxf(lv, ov);
            }
            if ((tid & 31) == 0) {
                SSv[r * 4 + wir] = bs; SSi[r * 4 + wir] = bi; SVm[r * 4 + wir] = lv;
            }
            __syncthreads();

            float vmax = SVm[r * 4];
#pragma unroll
            for (int w = 1; w < 4; w++) vmax = fmaxf(vmax, SVm[r * 4 + w]);

            float es = 0.0f;
#pragma unroll
            for (int q = 0; q < 4; q++)
                es = __fadd_rn(es, expf(__fsub_rn(vq[q], vmax)));
#pragma unroll
            for (int off = 16; off > 0; off >>= 1)
                es = __fadd_rn(es, __shfl_xor_sync(0xFFFFFFFFu, es, off));
            if ((tid & 31) == 0) SEx[r * 4 + wir] = es;
            __syncthreads();

            if (c0 == 0) {
                float fs = SSv[r * 4]; int fi = SSi[r * 4];
                float S  = SEx[r * 4];
#pragma unroll
                for (int w = 1; w < 4; w++) {
                    float os = SSv[r * 4 + w]; int oi = SSi[r * 4 + w];
                    if (os > fs || (os == fs && oi < fi)) { fs = os; fi = oi; }
                    S = __fadd_rn(S, SEx[r * 4 + w]);
                }
                int idx = fi;
                float vsel = __ldcg(&g_logits[(size_t)b * NN + idx]);   // idx is available
                float ps = __fdiv_rn(expf(__fsub_rn(vsel, vmax)), S);
                float lp = __fadd_rn(g_lp[b], logf(__fadd_rn(ps, 1e-9f)));
                g_lp[b]  = lp;
                g_sel[b] = idx;
                g_avail[b * 16 + (idx >> 5)] &= ~(1u << (idx & 31));
                out[(size_t)b * NN * NN + (size_t)t * NN + idx] = 1.0f;
                if (t == NN - 1) out[(size_t)BB * NN * NN + b] = lp;
            }
        }
        gsync();
    }
}

// -------- host launcher: 2 graph nodes (memset + persistent kernel) --------
extern "C" void kernel_launch(void* const* d_in, const int* in_sizes, int n_in,
                              void* d_out, int out_size)
{
    int base = (n_in == 11) ? 1 : 0;   // batch_size scalar first per metadata
    const float* Wih0 = (const float*)d_in[base + 0];
    const float* Whh0 = (const float*)d_in[base + 1];
    const float* bih0 = (const float*)d_in[base + 2];
    const float* bhh0 = (const float*)d_in[base + 3];
    const float* Wih1 = (const float*)d_in[base + 4];
    const float* Whh1 = (const float*)d_in[base + 5];
    const float* bih1 = (const float*)d_in[base + 6];
    const float* bhh1 = (const float*)d_in[base + 7];
    const float* Wout = (const float*)d_in[base + 8];
    const float* bout = (const float*)d_in[base + 9];
    float* out = (float*)d_out;
    (void)in_sizes;

    size_t shbytes = (size_t)SMEMF * sizeof(float);   // 69632 B
    cudaFuncSetAttribute(perm_persistent,
                         cudaFuncAttributeMaxDynamicSharedMemorySize, (int)shbytes);

    cudaMemsetAsync(d_out, 0, (size_t)out_size * sizeof(float), 0);
    perm_persistent<<<GBLK, NTHR, shbytes>>>(Wih0, Whh0, bih0, bhh0,
                                             Wih1, Whh1, bih1, bhh1,
                                             Wout, bout, out);
}